// round 4
// baseline (speedup 1.0000x reference)
#include <cuda_runtime.h>
#include <cstdint>

#define NN 10000
#define EE 80000
#define TASKS 576          // 48 batch * 12 (h,k)
#define HKN 12
#define CHUNK 16
#define MAXE 96
#define GSTRIDE 388

// dynamic smem layout (float words)
#define OFF_SD   0          // 576
#define OFF_ID   576        // 576
#define OFF_W    1152       // 12288  (W [384][32])
#define OFF_UNI  13440      // 9344   (union: wsh 16*576 | gsh 24*388 | psh 4*24*33)
#define OFF_EID  22784      // 96 ints
#define OFF_ESRC 22880      // 96 ints
#define SMEM_WORDS 22976
#define SMEM_BYTES (SMEM_WORDS * 4)

// ---------------- static scratch (allowed) ----------------
__device__ float d_s_src[NN * TASKS];      // 23 MB  [n][b*12+hk]
__device__ float d_s_dst[NN * TASKS];      // 23 MB
__device__ float d_wa_src[HKN * 32];
__device__ float d_wa_dst[HKN * 32];
__device__ int   d_deg[NN];
__device__ int   d_off[NN + 1];
__device__ int   d_cur[NN];
__device__ int   d_csr[EE];

// ---------------- f32x2 helpers ----------------
#define FMA2(d, a, b) \
    asm volatile("fma.rn.f32x2 %0, %1, %2, %0;" : "+l"(d) : "l"(a), "l"(b))
#define PACKDUP(o, v) \
    asm("mov.b64 %0, {%1, %1};" : "=l"(o) : "r"(__float_as_uint(v)))
#define UNPACK2(lo, hi, a) \
    asm("mov.b64 {%0, %1}, %2;" : "=r"(lo), "=r"(hi) : "l"(a))

// ---------------- K1: wa[hk][i] = sum_j W[hk][i][j] * a[h][j] ---------------
__global__ void k_wa(const float* __restrict__ W,
                     const float* __restrict__ a_src,
                     const float* __restrict__ a_dst) {
    int hk = blockIdx.x, i = threadIdx.x, h = hk / 3;
    float s1 = 0.f, s2 = 0.f;
    #pragma unroll
    for (int j = 0; j < 32; j++) {
        float w = W[hk * 1024 + i * 32 + j];
        s1 += w * a_src[h * 32 + j];
        s2 += w * a_dst[h * 32 + j];
    }
    d_wa_src[hk * 32 + i] = s1;
    d_wa_dst[hk * 32 + i] = s2;
}

// ---------------- K2: s_src/s_dst = x . wa ----------------
__global__ __launch_bounds__(192) void k_s(const float* __restrict__ x) {
    __shared__ float xsh[48][33];
    __shared__ float was[HKN][33];
    __shared__ float wad[HKN][33];
    int n = blockIdx.x, tid = threadIdx.x;
    for (int idx = tid; idx < 48 * 32; idx += 192) {
        int b = idx >> 5, i = idx & 31;
        xsh[b][i] = x[b * (NN * 32) + n * 32 + i];
    }
    for (int idx = tid; idx < HKN * 32; idx += 192) {
        int hk = idx >> 5, i = idx & 31;
        was[hk][i] = d_wa_src[idx];
        wad[hk][i] = d_wa_dst[idx];
    }
    __syncthreads();
    for (int t2 = tid; t2 < TASKS; t2 += 192) {
        int b = t2 / HKN, hk = t2 - b * HKN;
        float ss = 0.f, sd = 0.f;
        #pragma unroll
        for (int i = 0; i < 32; i++) {
            float xv = xsh[b][i];
            ss += xv * was[hk][i];
            sd += xv * wad[hk][i];
        }
        d_s_src[n * TASKS + t2] = ss;
        d_s_dst[n * TASKS + t2] = sd;
    }
}

// ---------------- CSR build ----------------
__global__ void k_zero() {
    int i = blockIdx.x * blockDim.x + threadIdx.x;
    if (i < NN) { d_deg[i] = 0; d_cur[i] = 0; }
}
__global__ void k_hist(const int* __restrict__ dst) {
    int e = blockIdx.x * blockDim.x + threadIdx.x;
    if (e < EE) atomicAdd(&d_deg[dst[e]], 1);
}
__global__ __launch_bounds__(1024) void k_scan() {
    __shared__ int sums[1024];
    const int CH = 10;
    int t = threadIdx.x, s = 0;
    for (int q = 0; q < CH; q++) {
        int i = t * CH + q;
        if (i < NN) s += d_deg[i];
    }
    sums[t] = s;
    __syncthreads();
    for (int o = 1; o < 1024; o <<= 1) {
        int v = (t >= o) ? sums[t - o] : 0;
        __syncthreads();
        sums[t] += v;
        __syncthreads();
    }
    int run = (t == 0) ? 0 : sums[t - 1];
    for (int q = 0; q < CH; q++) {
        int i = t * CH + q;
        if (i < NN) { d_off[i] = run; run += d_deg[i]; }
    }
    if (t == 1023) d_off[NN] = sums[1023];
}
__global__ void k_scatter(const int* __restrict__ dst) {
    int e = blockIdx.x * blockDim.x + threadIdx.x;
    if (e < EE) {
        int d = dst[e];
        int p = d_off[d] + atomicAdd(&d_cur[d], 1);
        d_csr[p] = e;
    }
}

// ---------------- K4: fused softmax + aggregate + GEMM + epilogue ----------
__global__ __launch_bounds__(384, 2) void k_fused(const float* __restrict__ x,
                                                  const int* __restrict__ src,
                                                  const float* __restrict__ sw,
                                                  const float* __restrict__ W,
                                                  float* __restrict__ out) {
    extern __shared__ float sm[];
    float* sdsh = sm + OFF_SD;
    float* idsh = sm + OFF_ID;
    float* Wsh  = sm + OFF_W;
    float* uni  = sm + OFF_UNI;
    int*   eidsh = (int*)(sm + OFF_EID);
    int*   esrch = (int*)(sm + OFF_ESRC);

    int d = blockIdx.x, tid = threadIdx.x;
    int w = tid >> 5, lane = tid & 31;
    int base = d_off[d];
    int deg  = d_off[d + 1] - base;

    // load W tile (always; needed unless deg==0)
    if (deg > 0) {
        const float4* Wg = (const float4*)W;
        float4* Ws4 = (float4*)Wsh;
        for (int i = tid; i < 3072; i += 384) Ws4[i] = Wg[i];
    }

    if (deg == 0) {     // no in-edges: out = relu(x)
        for (int idx = tid; idx < 48 * 32; idx += 384) {
            int b = idx >> 5, i = idx & 31;
            int o = b * (NN * 32) + d * 32 + i;
            float v = x[o];
            out[o] = v > 0.f ? v : 0.f;
        }
        return;
    }

    int degc = deg < MAXE ? deg : MAXE;
    for (int t2 = tid; t2 < TASKS; t2 += 384) sdsh[t2] = d_s_dst[d * TASKS + t2];
    for (int e = tid; e < degc; e += 384) eidsh[e] = d_csr[base + e];
    __syncthreads();
    if (tid == 0 && degc > 1) {            // deterministic edge order
        for (int a = 1; a < degc; a++) {
            int key = eidsh[a], b2 = a - 1;
            while (b2 >= 0 && eidsh[b2] > key) { eidsh[b2 + 1] = eidsh[b2]; b2--; }
            eidsh[b2 + 1] = key;
        }
    }
    __syncthreads();
    for (int e = tid; e < degc; e += 384) esrch[e] = src[eidsh[e]];
    __syncthreads();

    // ---- Phase A: denominators (no max-sub; logits are O(1)) ----
    for (int t2 = tid; t2 < TASKS; t2 += 384) {
        float sdv = sdsh[t2];
        float den = 0.f;
        float v = d_s_src[esrch[0] * TASKS + t2];
        for (int e = 0; e < deg; e++) {
            float l = v + sdv;
            if (e + 1 < deg) {
                int sn = (e + 1 < degc) ? esrch[e + 1] : src[d_csr[base + e + 1]];
                v = d_s_src[sn * TASKS + t2];
            }
            l = l > 0.f ? l : 0.2f * l;
            den += __expf(l);
        }
        idsh[t2] = 1.0f / (den + 1e-9f);
    }

    // ---- Phase B: g[b][hk] (x-space aggregation), chunked ----
    float g[4][HKN];
    #pragma unroll
    for (int bb = 0; bb < 4; bb++)
        #pragma unroll
        for (int hk = 0; hk < HKN; hk++) g[bb][hk] = 0.f;

    int xoff[4];
    #pragma unroll
    for (int bb = 0; bb < 4; bb++) xoff[bb] = (w + 12 * bb) * (NN * 32) + lane;

    float* wsh = uni;
    for (int cs = 0; cs < deg; cs += CHUNK) {
        int ce = min(CHUNK, deg - cs);
        __syncthreads();
        for (int idx = tid; idx < ce * TASKS; idx += 384) {
            int el = idx / TASKS;
            int t2 = idx - el * TASKS;
            int ee = cs + el;
            int eid = (ee < degc) ? eidsh[ee] : d_csr[base + ee];
            int s   = (ee < degc) ? esrch[ee] : src[eid];
            float l = d_s_src[s * TASKS + t2] + sdsh[t2];
            l = l > 0.f ? l : 0.2f * l;
            wsh[idx] = __expf(l) * idsh[t2] * sw[(t2 % 3) * EE + eid];
        }
        __syncthreads();
        int s0 = (cs < degc) ? esrch[cs] : src[d_csr[base + cs]];
        float xv[4];
        #pragma unroll
        for (int bb = 0; bb < 4; bb++) xv[bb] = x[xoff[bb] + s0 * 32];
        for (int el = 0; el < ce; el++) {
            float xn[4];
            if (el + 1 < ce) {
                int ee = cs + el + 1;
                int sn = (ee < degc) ? esrch[ee] : src[d_csr[base + ee]];
                #pragma unroll
                for (int bb = 0; bb < 4; bb++) xn[bb] = x[xoff[bb] + sn * 32];
            } else {
                #pragma unroll
                for (int bb = 0; bb < 4; bb++) xn[bb] = 0.f;
            }
            const float4* wrow = (const float4*)&wsh[el * TASKS];
            #pragma unroll
            for (int bb = 0; bb < 4; bb++) {
                int b = w + 12 * bb;
                float4 w0 = wrow[b * 3 + 0];
                float4 w1 = wrow[b * 3 + 1];
                float4 w2 = wrow[b * 3 + 2];
                float xb = xv[bb];
                g[bb][0]  += w0.x * xb;  g[bb][1]  += w0.y * xb;
                g[bb][2]  += w0.z * xb;  g[bb][3]  += w0.w * xb;
                g[bb][4]  += w1.x * xb;  g[bb][5]  += w1.y * xb;
                g[bb][6]  += w1.z * xb;  g[bb][7]  += w1.w * xb;
                g[bb][8]  += w2.x * xb;  g[bb][9]  += w2.y * xb;
                g[bb][10] += w2.z * xb;  g[bb][11] += w2.w * xb;
            }
            #pragma unroll
            for (int bb = 0; bb < 4; bb++) xv[bb] = xn[bb];
        }
    }

    // ---- Phase C: out = relu(g @ W / 4 + x), two 24-batch rounds ----
    int grp = tid / 96;               // k-quarter
    int gt  = tid - grp * 96;
    int bg  = gt >> 3;                // 0..11
    int j4  = gt & 7;                 // 4 output cols
    uint32_t wbase;
    { uint32_t a = (uint32_t)__cvta_generic_to_shared(Wsh); wbase = a + j4 * 16; }

    for (int r = 0; r < 2; r++) {
        __syncthreads();
        float* gsh = uni;             // [24][GSTRIDE]
        #pragma unroll
        for (int bb2 = 0; bb2 < 2; bb2++) {
            int bl = w + 12 * bb2;
            int bbg = 2 * r + bb2;
            #pragma unroll
            for (int hk = 0; hk < HKN; hk++)
                gsh[bl * GSTRIDE + hk * 32 + lane] = g[bbg][hk];
        }
        __syncthreads();

        unsigned long long acc00 = 0, acc01 = 0, acc10 = 0, acc11 = 0;
        const float* ga_p = &gsh[bg * GSTRIDE];
        const float* gb_p = &gsh[(bg + 12) * GSTRIDE];
        for (int k0 = grp * 96; k0 < grp * 96 + 96; k0 += 4) {
            float4 ga = *(const float4*)&ga_p[k0];
            float4 gb = *(const float4*)&gb_p[k0];
            #pragma unroll
            for (int kk = 0; kk < 4; kk++) {
                float gav = (kk == 0) ? ga.x : (kk == 1) ? ga.y : (kk == 2) ? ga.z : ga.w;
                float gbv = (kk == 0) ? gb.x : (kk == 1) ? gb.y : (kk == 2) ? gb.z : gb.w;
                unsigned long long w01, w23, ga2, gb2;
                uint32_t addr = wbase + (uint32_t)(k0 + kk) * 128u;
                asm volatile("ld.shared.v2.u64 {%0, %1}, [%2];"
                             : "=l"(w01), "=l"(w23) : "r"(addr));
                PACKDUP(ga2, gav);
                PACKDUP(gb2, gbv);
                FMA2(acc00, ga2, w01);
                FMA2(acc01, ga2, w23);
                FMA2(acc10, gb2, w01);
                FMA2(acc11, gb2, w23);
            }
        }
        __syncthreads();
        float* psh = uni;             // [4][24][33]
        {
            uint32_t l0, h0, l1, h1;
            UNPACK2(l0, h0, acc00); UNPACK2(l1, h1, acc01);
            float* p = &psh[(grp * 24 + bg) * 33 + j4 * 4];
            p[0] = __uint_as_float(l0); p[1] = __uint_as_float(h0);
            p[2] = __uint_as_float(l1); p[3] = __uint_as_float(h1);
            UNPACK2(l0, h0, acc10); UNPACK2(l1, h1, acc11);
            p = &psh[(grp * 24 + bg + 12) * 33 + j4 * 4];
            p[0] = __uint_as_float(l0); p[1] = __uint_as_float(h0);
            p[2] = __uint_as_float(l1); p[3] = __uint_as_float(h1);
        }
        __syncthreads();
        for (int idx = tid; idx < 24 * 32; idx += 384) {
            int bl = idx >> 5, j = idx & 31;
            float v = psh[bl * 33 + j] + psh[(24 + bl) * 33 + j]
                    + psh[(48 + bl) * 33 + j] + psh[(72 + bl) * 33 + j];
            int o = (bl + 24 * r) * (NN * 32) + d * 32 + j;
            float res = v * 0.25f + x[o];
            out[o] = res > 0.f ? res : 0.f;
        }
    }
}

// ---------------- launch ----------------
extern "C" void kernel_launch(void* const* d_in, const int* in_sizes, int n_in,
                              void* d_out, int out_size) {
    (void)in_sizes; (void)n_in; (void)out_size;
    const float* x     = (const float*)d_in[0];   // [48][10000][32]
    const int*   src   = (const int*)  d_in[1];   // [80000]
    const int*   dst   = (const int*)  d_in[2];   // [80000]
    const float* sw    = (const float*)d_in[3];   // [3][80000]
    const float* W     = (const float*)d_in[4];   // [12*32][32]
    const float* a_src = (const float*)d_in[5];   // [4][32]
    const float* a_dst = (const float*)d_in[6];   // [4][32]
    float*       out   = (float*)d_out;           // [48][10000][32]

    cudaFuncSetAttribute(k_fused, cudaFuncAttributeMaxDynamicSharedMemorySize,
                         SMEM_BYTES);

    k_wa<<<12, 32>>>(W, a_src, a_dst);
    k_s<<<NN, 192>>>(x);
    k_zero<<<(NN + 255) / 256, 256>>>();
    k_hist<<<(EE + 255) / 256, 256>>>(dst);
    k_scan<<<1, 1024>>>();
    k_scatter<<<(EE + 255) / 256, 256>>>(dst);
    k_fused<<<NN, 384, SMEM_BYTES>>>(x, src, sw, W, out);
}

// round 7
// speedup vs baseline: 1.4834x; 1.4834x over previous
#include <cuda_runtime.h>
#include <cuda_fp16.h>
#include <cstdint>

#define NN 10000
#define EE 80000
#define TASKS 576          // 48 batch * 12 (h,k)
#define HKN 12
#define CHUNK 16
#define MAXE 96
#define GS 392             // padded stride (halves) for gsh / WT

// dynamic smem layout (float words)
#define OFF_SD   0          // 576
#define OFF_ID   576        // 576
#define OFF_WT   1152       // 6272 words = 32*392 halves
#define OFF_UNI  7424       // 9408 words (union: wsh 16*576 fl | gsh 48*392 halves)
#define OFF_SW   16832      // 288  (sw staged [3][MAXE])
#define OFF_EID  17120      // 96 ints
#define OFF_ESRC 17216      // 96 ints
#define SMEM_WORDS 17312
#define SMEM_BYTES (SMEM_WORDS * 4)   // 69248

// ---------------- static scratch ----------------
__device__ float d_s_src[NN * TASKS];      // 23 MB [n][b*12+hk]
__device__ float d_s_dst[NN * TASKS];      // 23 MB
__device__ float d_wa_src[HKN * 32];
__device__ float d_wa_dst[HKN * 32];
__device__ __align__(16) __half d_wt[32 * GS];   // W fp16, [j][k'=i*12+hk]
__device__ int   d_deg[NN];
__device__ int   d_off[NN + 1];
__device__ int   d_cur[NN];
__device__ int   d_csr[EE];

// ---------------- f32x2 helpers ----------------
#define FMA2(d, a, b) \
    asm volatile("fma.rn.f32x2 %0, %1, %2, %0;" : "+l"(d) : "l"(a), "l"(b))
#define MUL2(d, a, b) \
    asm("mul.rn.f32x2 %0, %1, %2;" : "=l"(d) : "l"(a), "l"(b))
#define PACKDUP(o, v) \
    asm("mov.b64 %0, {%1, %1};" : "=l"(o) : "r"(__float_as_uint(v)))
#define UNPACK2(lo, hi, a) \
    asm("mov.b64 {%0, %1}, %2;" : "=r"(lo), "=r"(hi) : "l"(a))
// pack {lo,hi} fp32 -> f16x2 (PTX: cvt d,a,b -> d={hi=a,lo=b})
#define CVTH2(r, hi, lo) \
    asm("cvt.rn.f16x2.f32 %0, %1, %2;" : "=r"(r) : "f"(hi), "f"(lo))

// ---------------- K1: wa = W @ a ----------------
__global__ void k_wa(const float* __restrict__ W,
                     const float* __restrict__ a_src,
                     const float* __restrict__ a_dst) {
    int hk = blockIdx.x, i = threadIdx.x, h = hk / 3;
    float s1 = 0.f, s2 = 0.f;
    #pragma unroll
    for (int j = 0; j < 32; j++) {
        float w = W[hk * 1024 + i * 32 + j];
        s1 += w * a_src[h * 32 + j];
        s2 += w * a_dst[h * 32 + j];
    }
    d_wa_src[hk * 32 + i] = s1;
    d_wa_dst[hk * 32 + i] = s2;
}

// ---------------- K1b: W -> fp16 transposed  WT[j][i*12+hk] ----------------
__global__ void k_wprep(const float* __restrict__ W) {
    int j = blockIdx.x;          // 0..31 output col
    int kp = threadIdx.x;        // 0..383 k' = i*12+hk
    int i = kp / 12, hk = kp - i * 12;
    d_wt[j * GS + kp] = __float2half(W[hk * 1024 + i * 32 + j]);
    if (kp < GS - 384) d_wt[j * GS + 384 + kp] = __float2half(0.f);
}

// ---------------- K2: s_src/s_dst = x . wa ----------------
__global__ __launch_bounds__(192) void k_s(const float* __restrict__ x) {
    __shared__ float xsh[48][33];
    __shared__ float was[HKN][33];
    __shared__ float wad[HKN][33];
    int n = blockIdx.x, tid = threadIdx.x;
    for (int idx = tid; idx < 48 * 32; idx += 192) {
        int b = idx >> 5, i = idx & 31;
        xsh[b][i] = x[b * (NN * 32) + n * 32 + i];
    }
    for (int idx = tid; idx < HKN * 32; idx += 192) {
        int hk = idx >> 5, i = idx & 31;
        was[hk][i] = d_wa_src[idx];
        wad[hk][i] = d_wa_dst[idx];
    }
    __syncthreads();
    for (int t2 = tid; t2 < TASKS; t2 += 192) {
        int b = t2 / HKN, hk = t2 - b * HKN;
        float ss = 0.f, sd = 0.f;
        #pragma unroll
        for (int i = 0; i < 32; i++) {
            float xv = xsh[b][i];
            ss += xv * was[hk][i];
            sd += xv * wad[hk][i];
        }
        d_s_src[n * TASKS + t2] = ss;
        d_s_dst[n * TASKS + t2] = sd;
    }
}

// ---------------- CSR build ----------------
__global__ void k_zero() {
    int i = blockIdx.x * blockDim.x + threadIdx.x;
    if (i < NN) { d_deg[i] = 0; d_cur[i] = 0; }
}
__global__ void k_hist(const int* __restrict__ dst) {
    int e = blockIdx.x * blockDim.x + threadIdx.x;
    if (e < EE) atomicAdd(&d_deg[dst[e]], 1);
}
__global__ __launch_bounds__(1024) void k_scan() {
    __shared__ int sums[1024];
    const int CH = 10;
    int t = threadIdx.x, s = 0;
    for (int q = 0; q < CH; q++) {
        int i = t * CH + q;
        if (i < NN) s += d_deg[i];
    }
    sums[t] = s;
    __syncthreads();
    for (int o = 1; o < 1024; o <<= 1) {
        int v = (t >= o) ? sums[t - o] : 0;
        __syncthreads();
        sums[t] += v;
        __syncthreads();
    }
    int run = (t == 0) ? 0 : sums[t - 1];
    for (int q = 0; q < CH; q++) {
        int i = t * CH + q;
        if (i < NN) { d_off[i] = run; run += d_deg[i]; }
    }
    if (t == 1023) d_off[NN] = sums[1023];
}
__global__ void k_scatter(const int* __restrict__ dst) {
    int e = blockIdx.x * blockDim.x + threadIdx.x;
    if (e < EE) {
        int d = dst[e];
        int p = d_off[d] + atomicAdd(&d_cur[d], 1);
        d_csr[p] = e;
    }
}

// ---------------- K4: fused softmax + aggregate + HMMA GEMM ----------------
__global__ __launch_bounds__(384, 2) void k_fused(const float* __restrict__ x,
                                                  const int* __restrict__ src,
                                                  const float* __restrict__ sw,
                                                  float* __restrict__ out) {
    extern __shared__ float sm[];
    float*  sdsh  = sm + OFF_SD;
    float*  idsh  = sm + OFF_ID;
    __half* WTsh  = (__half*)(sm + OFF_WT);
    float*  wsh   = sm + OFF_UNI;                 // union: A2/B edge weights
    __half* gsh   = (__half*)(sm + OFF_UNI);      // union: fp16 g for HMMA
    float*  swsh  = sm + OFF_SW;
    int*    eidsh = (int*)(sm + OFF_EID);
    int*    esrch = (int*)(sm + OFF_ESRC);

    int d = blockIdx.x, tid = threadIdx.x;
    int w = tid >> 5, lane = tid & 31;
    int base = d_off[d];
    int deg  = d_off[d + 1] - base;

    if (deg == 0) {                 // no in-edges: out = relu(x)
        for (int idx = tid; idx < 48 * 32; idx += 384) {
            int b = idx >> 5, i = idx & 31;
            int o = b * (NN * 32) + d * 32 + i;
            float v = x[o];
            out[o] = v > 0.f ? v : 0.f;
        }
        return;
    }
    int degc = deg < MAXE ? deg : MAXE;

    // stage: s_dst row, edge ids, WT tile
    for (int t2 = tid; t2 < TASKS; t2 += 384) sdsh[t2] = d_s_dst[d * TASKS + t2];
    for (int e = tid; e < degc; e += 384) eidsh[e] = d_csr[base + e];
    {
        const uint4* wg = (const uint4*)d_wt;
        uint4* ws = (uint4*)WTsh;
        for (int i = tid; i < (32 * GS) / 8; i += 384) ws[i] = wg[i];
    }
    __syncthreads();
    if (tid == 0 && degc > 1) {     // deterministic edge order
        for (int a = 1; a < degc; a++) {
            int key = eidsh[a], b2 = a - 1;
            while (b2 >= 0 && eidsh[b2] > key) { eidsh[b2 + 1] = eidsh[b2]; b2--; }
            eidsh[b2 + 1] = key;
        }
    }
    __syncthreads();
    for (int e = tid; e < degc; e += 384) esrch[e] = src[eidsh[e]];
    for (int idx = tid; idx < 3 * degc; idx += 384) {
        int k = idx / degc, e = idx - k * degc;
        swsh[k * MAXE + e] = sw[k * EE + eidsh[e]];
    }
    __syncthreads();

    // accumulators: gg[bb][p] = f32x2 pair (hk=2p, 2p+1), lane = input dim i
    unsigned long long gg[4][6];
    #pragma unroll
    for (int bb = 0; bb < 4; bb++)
        #pragma unroll
        for (int p = 0; p < 6; p++) gg[bb][p] = 0ull;
    int xoff[4];
    #pragma unroll
    for (int bb = 0; bb < 4; bb++) xoff[bb] = (w + 12 * bb) * (NN * 32) + lane;

    float den0 = 0.f, den1 = 0.f;

    for (int cs = 0; cs < deg; cs += CHUNK) {
        int ce = min(CHUNK, deg - cs);
        __syncthreads();            // wsh free from previous Phase B
        // ---- Phase A2: unnormalized weights + den accumulation (t2-major) --
        #pragma unroll
        for (int q = 0; q < 2; q++) {
            int t2 = tid + 384 * q;
            if (t2 < TASKS) {
                float sdv = sdsh[t2];
                int kk = t2 % 3;
                float dacc = 0.f;
                for (int el = 0; el < ce; el++) {
                    int ee = cs + el;
                    int s; float swv;
                    if (ee < degc) { s = esrch[ee]; swv = swsh[kk * MAXE + ee]; }
                    else { int eid = d_csr[base + ee]; s = src[eid]; swv = sw[kk * EE + eid]; }
                    float l = d_s_src[s * TASKS + t2] + sdv;
                    l = l > 0.f ? l : 0.2f * l;
                    float ev = __expf(l);
                    dacc += ev;
                    wsh[el * TASKS + t2] = ev * swv;
                }
                if (q) den1 += dacc; else den0 += dacc;
            }
        }
        __syncthreads();
        // ---- Phase B: gg += wsh * x[src] (f32x2) ----
        int s0 = (cs < degc) ? esrch[cs] : src[d_csr[base + cs]];
        float xv[4], xn[4];
        #pragma unroll
        for (int bb = 0; bb < 4; bb++) xv[bb] = x[xoff[bb] + s0 * 32];
        for (int el = 0; el < ce; el++) {
            if (el + 1 < ce) {
                int ee = cs + el + 1;
                int sn = (ee < degc) ? esrch[ee] : src[d_csr[base + ee]];
                #pragma unroll
                for (int bb = 0; bb < 4; bb++) xn[bb] = x[xoff[bb] + sn * 32];
            } else {
                #pragma unroll
                for (int bb = 0; bb < 4; bb++) xn[bb] = 0.f;
            }
            const ulonglong2* wp = (const ulonglong2*)&wsh[el * TASKS];
            #pragma unroll
            for (int bb = 0; bb < 4; bb++) {
                int b = w + 12 * bb;
                ulonglong2 w01 = wp[b * 3 + 0];
                ulonglong2 w23 = wp[b * 3 + 1];
                ulonglong2 w45 = wp[b * 3 + 2];
                unsigned long long xb2;
                PACKDUP(xb2, xv[bb]);
                FMA2(gg[bb][0], xb2, w01.x);
                FMA2(gg[bb][1], xb2, w01.y);
                FMA2(gg[bb][2], xb2, w23.x);
                FMA2(gg[bb][3], xb2, w23.y);
                FMA2(gg[bb][4], xb2, w45.x);
                FMA2(gg[bb][5], xb2, w45.y);
            }
            #pragma unroll
            for (int bb = 0; bb < 4; bb++) xv[bb] = xn[bb];
        }
    }

    // ---- denominators -> idsh ----
    #pragma unroll
    for (int q = 0; q < 2; q++) {
        int t2 = tid + 384 * q;
        if (t2 < TASKS) idsh[t2] = 1.0f / ((q ? den1 : den0) + 1e-9f);
    }
    __syncthreads();

    // ---- scale by 1/den, convert to fp16, store gsh[b][k'=i*12+hk] ----
    uint32_t gbase = (uint32_t)__cvta_generic_to_shared(gsh);
    #pragma unroll
    for (int bb = 0; bb < 4; bb++) {
        int b = w + 12 * bb;
        const unsigned long long* ip = (const unsigned long long*)&idsh[b * 12];
        uint32_t h2[6];
        #pragma unroll
        for (int p = 0; p < 6; p++) {
            unsigned long long gv;
            MUL2(gv, gg[bb][p], ip[p]);
            uint32_t lo, hi;
            UNPACK2(lo, hi, gv);
            CVTH2(h2[p], __uint_as_float(hi), __uint_as_float(lo));
        }
        uint32_t sa = gbase + (uint32_t)(b * (GS * 2) + lane * 24);
        asm volatile("st.shared.v2.u32 [%0], {%1, %2};" :: "r"(sa), "r"(h2[0]), "r"(h2[1]));
        asm volatile("st.shared.v2.u32 [%0], {%1, %2};" :: "r"(sa + 8), "r"(h2[2]), "r"(h2[3]));
        asm volatile("st.shared.v2.u32 [%0], {%1, %2};" :: "r"(sa + 16), "r"(h2[4]), "r"(h2[5]));
    }
    __syncthreads();

    // ---- Phase C: HMMA  out = relu(gsh @ WT / 4 + x) ----
    // warp w -> (mi = w/4) m16-tile, (nj = w%4) n8-tile; K loop 24 x k16
    {
        int mi = w >> 2, nj = w & 3;
        uint32_t arow = gbase + (uint32_t)(((mi * 16 + (lane & 15)) * GS + ((lane >> 4) * 8)) * 2);
        const __half* wtp = &WTsh[(nj * 8 + (lane >> 2)) * GS + (lane & 3) * 2];
        float c0 = 0.f, c1 = 0.f, c2 = 0.f, c3 = 0.f;
        #pragma unroll
        for (int kb = 0; kb < 24; kb++) {
            int k0 = kb * 16;
            uint32_t a0, a1, a2, a3;
            asm volatile("ldmatrix.sync.aligned.m8n8.x4.shared.b16 {%0,%1,%2,%3}, [%4];"
                         : "=r"(a0), "=r"(a1), "=r"(a2), "=r"(a3)
                         : "r"(arow + (uint32_t)(k0 * 2)));
            uint32_t b0 = *(const uint32_t*)&wtp[k0];
            uint32_t b1 = *(const uint32_t*)&wtp[k0 + 8];
            asm volatile("mma.sync.aligned.m16n8k16.row.col.f32.f16.f16.f32 "
                         "{%0,%1,%2,%3},{%4,%5,%6,%7},{%8,%9},{%0,%1,%2,%3};"
                         : "+f"(c0), "+f"(c1), "+f"(c2), "+f"(c3)
                         : "r"(a0), "r"(a1), "r"(a2), "r"(a3), "r"(b0), "r"(b1));
        }
        int bl = mi * 16 + (lane >> 2);
        int j  = nj * 8 + (lane & 3) * 2;
        int o  = bl * (NN * 32) + d * 32 + j;
        float2 xv0 = *(const float2*)&x[o];
        float2 r0;
        r0.x = fmaxf(c0 * 0.25f + xv0.x, 0.f);
        r0.y = fmaxf(c1 * 0.25f + xv0.y, 0.f);
        *(float2*)&out[o] = r0;
        o += 8 * (NN * 32);
        float2 xv1 = *(const float2*)&x[o];
        float2 r1;
        r1.x = fmaxf(c2 * 0.25f + xv1.x, 0.f);
        r1.y = fmaxf(c3 * 0.25f + xv1.y, 0.f);
        *(float2*)&out[o] = r1;
    }
}

// ---------------- launch ----------------
extern "C" void kernel_launch(void* const* d_in, const int* in_sizes, int n_in,
                              void* d_out, int out_size) {
    (void)in_sizes; (void)n_in; (void)out_size;
    const float* x     = (const float*)d_in[0];   // [48][10000][32]
    const int*   src   = (const int*)  d_in[1];
    const int*   dst   = (const int*)  d_in[2];
    const float* sw    = (const float*)d_in[3];   // [3][80000]
    const float* W     = (const float*)d_in[4];   // [12*32][32]
    const float* a_src = (const float*)d_in[5];
    const float* a_dst = (const float*)d_in[6];
    float*       out   = (float*)d_out;

    cudaFuncSetAttribute(k_fused, cudaFuncAttributeMaxDynamicSharedMemorySize,
                         SMEM_BYTES);

    k_wa<<<12, 32>>>(W, a_src, a_dst);
    k_wprep<<<32, 384>>>(W);
    k_s<<<NN, 192>>>(x);
    k_zero<<<(NN + 255) / 256, 256>>>();
    k_hist<<<(EE + 255) / 256, 256>>>(dst);
    k_scan<<<1, 1024>>>();
    k_scatter<<<(EE + 255) / 256, 256>>>(dst);
    k_fused<<<NN, 384, SMEM_BYTES>>>(x, src, sw, out);
}